// round 1
// baseline (speedup 1.0000x reference)
#include <cuda_runtime.h>
#include <math.h>

// Problem constants
#define Bn   16
#define Ls   1024
#define Lh   1024
#define Dd   1024      // D1 == D2 == 1024

#define BM 128
#define BN 128
#define BK 16

// 64 MB scratch each (device globals: allowed; no allocation APIs).
__device__ float g_Sp[(size_t)Bn * Ls * Dd];     // S @ W^T + b
__device__ float g_score[(size_t)Bn * Ls * Lh];  // scores / softmax probs

// ---------------------------------------------------------------------------
// NT GEMM: C[m][n] = sum_k A[m][k] * B[n][k]  (+ bias[n]) (+ mask[m][n])
// A: [M,K] row-major, B: [N,K] row-major, C: [M,N] row-major.
// Batched via blockIdx.z with element strides sA/sB/sC/sMask.
// All dims assumed multiples of tile sizes (true here).
// ---------------------------------------------------------------------------
__global__ __launch_bounds__(256) void sgemm_nt(
    const float* __restrict__ A, const float* __restrict__ B,
    float* __restrict__ C,
    const float* __restrict__ bias, const float* __restrict__ mask,
    int M, int N, int K,
    size_t sA, size_t sB, size_t sC, size_t sMask)
{
    __shared__ float As[BK][BM];
    __shared__ float Bs[BK][BN];

    const int bz = blockIdx.z;
    A += (size_t)bz * sA;
    B += (size_t)bz * sB;
    C += (size_t)bz * sC;
    if (mask) mask += (size_t)bz * sMask;

    const int m0 = blockIdx.y * BM;
    const int n0 = blockIdx.x * BN;
    const int tid = threadIdx.x;
    const int tx = tid & 15;        // 0..15
    const int ty = tid >> 4;        // 0..15
    const int tm = ty * 4;
    const int tn = tx * 4;

    float acc[8][8];
    #pragma unroll
    for (int i = 0; i < 8; i++)
        #pragma unroll
        for (int j = 0; j < 8; j++) acc[i][j] = 0.0f;

    for (int k0 = 0; k0 < K; k0 += BK) {
        // Load tiles: 512 float4 per operand; each thread does 2.
        #pragma unroll
        for (int r = 0; r < 2; r++) {
            int i  = tid + r * 256;        // 0..511
            int mm = i >> 2;               // 0..127
            int kq = (i & 3) * 4;          // 0,4,8,12
            float4 va = *reinterpret_cast<const float4*>(
                &A[(size_t)(m0 + mm) * K + k0 + kq]);
            As[kq + 0][mm] = va.x;
            As[kq + 1][mm] = va.y;
            As[kq + 2][mm] = va.z;
            As[kq + 3][mm] = va.w;
            float4 vb = *reinterpret_cast<const float4*>(
                &B[(size_t)(n0 + mm) * K + k0 + kq]);
            Bs[kq + 0][mm] = vb.x;
            Bs[kq + 1][mm] = vb.y;
            Bs[kq + 2][mm] = vb.z;
            Bs[kq + 3][mm] = vb.w;
        }
        __syncthreads();

        #pragma unroll
        for (int k = 0; k < BK; k++) {
            float a[8], b[8];
            *reinterpret_cast<float4*>(&a[0]) = *reinterpret_cast<const float4*>(&As[k][tm]);
            *reinterpret_cast<float4*>(&a[4]) = *reinterpret_cast<const float4*>(&As[k][tm + 64]);
            *reinterpret_cast<float4*>(&b[0]) = *reinterpret_cast<const float4*>(&Bs[k][tn]);
            *reinterpret_cast<float4*>(&b[4]) = *reinterpret_cast<const float4*>(&Bs[k][tn + 64]);
            #pragma unroll
            for (int i = 0; i < 8; i++)
                #pragma unroll
                for (int j = 0; j < 8; j++)
                    acc[i][j] = fmaf(a[i], b[j], acc[i][j]);
        }
        __syncthreads();
    }

    // Epilogue
    #pragma unroll
    for (int i = 0; i < 8; i++) {
        int m = m0 + tm + ((i < 4) ? i : 60 + i);  // tm+0..3, tm+64..67
        size_t rowoff = (size_t)m * N;
        #pragma unroll
        for (int jh = 0; jh < 2; jh++) {
            int n = n0 + tn + jh * 64;
            float4 v;
            v.x = acc[i][jh * 4 + 0];
            v.y = acc[i][jh * 4 + 1];
            v.z = acc[i][jh * 4 + 2];
            v.w = acc[i][jh * 4 + 3];
            if (bias) {
                v.x += bias[n + 0]; v.y += bias[n + 1];
                v.z += bias[n + 2]; v.w += bias[n + 3];
            }
            if (mask) {
                const float4 mk = *reinterpret_cast<const float4*>(&mask[rowoff + n]);
                v.x += mk.x; v.y += mk.y; v.z += mk.z; v.w += mk.w;
            }
            *reinterpret_cast<float4*>(&C[rowoff + n]) = v;
        }
    }
}

// ---------------------------------------------------------------------------
// NN GEMM: C[m][n] = sum_k A[m][k] * B[k][n]
// A: [M,K] row-major, B: [K,N] row-major, C: [M,N] row-major. Batched via z.
// ---------------------------------------------------------------------------
__global__ __launch_bounds__(256) void sgemm_nn(
    const float* __restrict__ A, const float* __restrict__ B,
    float* __restrict__ C,
    int M, int N, int K,
    size_t sA, size_t sB, size_t sC)
{
    __shared__ float As[BK][BM];
    __shared__ float Bs[BK][BN];

    const int bz = blockIdx.z;
    A += (size_t)bz * sA;
    B += (size_t)bz * sB;
    C += (size_t)bz * sC;

    const int m0 = blockIdx.y * BM;
    const int n0 = blockIdx.x * BN;
    const int tid = threadIdx.x;
    const int tx = tid & 15;
    const int ty = tid >> 4;
    const int tm = ty * 4;
    const int tn = tx * 4;

    float acc[8][8];
    #pragma unroll
    for (int i = 0; i < 8; i++)
        #pragma unroll
        for (int j = 0; j < 8; j++) acc[i][j] = 0.0f;

    for (int k0 = 0; k0 < K; k0 += BK) {
        #pragma unroll
        for (int r = 0; r < 2; r++) {
            int i  = tid + r * 256;
            // A: K-contiguous -> transpose into As[k][m]
            int mm = i >> 2;
            int kq = (i & 3) * 4;
            float4 va = *reinterpret_cast<const float4*>(
                &A[(size_t)(m0 + mm) * K + k0 + kq]);
            As[kq + 0][mm] = va.x;
            As[kq + 1][mm] = va.y;
            As[kq + 2][mm] = va.z;
            As[kq + 3][mm] = va.w;
            // B: N-contiguous -> direct float4 store into Bs[k][n]
            int kk = i >> 5;            // 0..15
            int nq = (i & 31) * 4;      // 0..124
            float4 vb = *reinterpret_cast<const float4*>(
                &B[(size_t)(k0 + kk) * N + n0 + nq]);
            *reinterpret_cast<float4*>(&Bs[kk][nq]) = vb;
        }
        __syncthreads();

        #pragma unroll
        for (int k = 0; k < BK; k++) {
            float a[8], b[8];
            *reinterpret_cast<float4*>(&a[0]) = *reinterpret_cast<const float4*>(&As[k][tm]);
            *reinterpret_cast<float4*>(&a[4]) = *reinterpret_cast<const float4*>(&As[k][tm + 64]);
            *reinterpret_cast<float4*>(&b[0]) = *reinterpret_cast<const float4*>(&Bs[k][tn]);
            *reinterpret_cast<float4*>(&b[4]) = *reinterpret_cast<const float4*>(&Bs[k][tn + 64]);
            #pragma unroll
            for (int i = 0; i < 8; i++)
                #pragma unroll
                for (int j = 0; j < 8; j++)
                    acc[i][j] = fmaf(a[i], b[j], acc[i][j]);
        }
        __syncthreads();
    }

    #pragma unroll
    for (int i = 0; i < 8; i++) {
        int m = m0 + tm + ((i < 4) ? i : 60 + i);
        size_t rowoff = (size_t)m * N;
        #pragma unroll
        for (int jh = 0; jh < 2; jh++) {
            int n = n0 + tn + jh * 64;
            float4 v;
            v.x = acc[i][jh * 4 + 0];
            v.y = acc[i][jh * 4 + 1];
            v.z = acc[i][jh * 4 + 2];
            v.w = acc[i][jh * 4 + 3];
            *reinterpret_cast<float4*>(&C[rowoff + n]) = v;
        }
    }
}

// ---------------------------------------------------------------------------
// Row softmax over rows of length 1024, in place. One block (256 thr) per row.
// ---------------------------------------------------------------------------
__global__ __launch_bounds__(256) void softmax_rows(float* __restrict__ P)
{
    __shared__ float red[8];
    const size_t row = blockIdx.x;
    float* p = P + row * 1024;
    const int tid  = threadIdx.x;
    const int lane = tid & 31;
    const int wid  = tid >> 5;

    float v[4];
    float mx = -INFINITY;
    #pragma unroll
    for (int i = 0; i < 4; i++) {
        v[i] = p[tid + i * 256];
        mx = fmaxf(mx, v[i]);
    }
    #pragma unroll
    for (int off = 16; off > 0; off >>= 1)
        mx = fmaxf(mx, __shfl_xor_sync(0xffffffffu, mx, off));
    if (lane == 0) red[wid] = mx;
    __syncthreads();
    {
        float m = red[lane & 7];
        #pragma unroll
        for (int off = 4; off > 0; off >>= 1)
            m = fmaxf(m, __shfl_xor_sync(0xffffffffu, m, off));
        mx = m;
    }

    float s = 0.0f;
    #pragma unroll
    for (int i = 0; i < 4; i++) {
        v[i] = expf(v[i] - mx);
        s += v[i];
    }
    #pragma unroll
    for (int off = 16; off > 0; off >>= 1)
        s += __shfl_xor_sync(0xffffffffu, s, off);
    __syncthreads();               // protect red[] reuse
    if (lane == 0) red[wid] = s;
    __syncthreads();
    {
        float t = red[lane & 7];
        #pragma unroll
        for (int off = 4; off > 0; off >>= 1)
            t += __shfl_xor_sync(0xffffffffu, t, off);
        s = t;
    }

    const float inv = 1.0f / s;
    #pragma unroll
    for (int i = 0; i < 4; i++)
        p[tid + i * 256] = v[i] * inv;
}

// ---------------------------------------------------------------------------
// Launch: S_ = S@W^T + b ; score = S_@H^T + mask ; softmax ; out = P@H
// Inputs (metadata order): S, H, pad_mask, W_w, W_b
// ---------------------------------------------------------------------------
extern "C" void kernel_launch(void* const* d_in, const int* in_sizes, int n_in,
                              void* d_out, int out_size)
{
    const float* S    = (const float*)d_in[0];
    const float* H    = (const float*)d_in[1];
    const float* mask = (const float*)d_in[2];
    const float* Ww   = (const float*)d_in[3];
    const float* Wb   = (const float*)d_in[4];
    float* out = (float*)d_out;

    float *Sp = nullptr, *Sc = nullptr;
    cudaGetSymbolAddress((void**)&Sp, g_Sp);
    cudaGetSymbolAddress((void**)&Sc, g_score);

    const size_t PB = (size_t)1024 * 1024;  // per-batch matrix stride
    dim3 blk(256);
    dim3 grid(Lh / BN, Ls / BM, Bn);        // 8 x 8 x 16

    // 1) S_ = S @ W^T + b   (W shared across batch: strideB = 0)
    sgemm_nt<<<grid, blk>>>(S, Ww, Sp, Wb, nullptr,
                            Ls, Dd, Dd, PB, 0, PB, 0);
    // 2) score = S_ @ H^T + pad_mask
    sgemm_nt<<<grid, blk>>>(Sp, H, Sc, nullptr, mask,
                            Ls, Lh, Dd, PB, PB, PB, PB);
    // 3) softmax over last axis (16*1024 rows)
    softmax_rows<<<Bn * Ls, 256>>>(Sc);
    // 4) out = P @ H
    sgemm_nn<<<grid, blk>>>(Sc, H, out,
                            Ls, Dd, Lh, PB, PB, PB);
}

// round 3
// speedup vs baseline: 1.2216x; 1.2216x over previous
#include <cuda_runtime.h>
#include <cuda_fp16.h>
#include <math.h>
#include <stdint.h>

// Problem constants
#define Bn    16
#define KDIM  1024
#define PB    ((size_t)1024 * 1024)

// GEMM tiling
#define BK      32            // halves per K chunk
#define NCHUNK  (KDIM / BK)   // 32
#define STRD    40            // padded smem row stride (halves) -> 80B
#define TILE_H  (128 * STRD)  // halves per tile buffer (5120)
#define OFF_AH  0
#define OFF_AL  (1 * TILE_H)
#define OFF_BH  (2 * TILE_H)
#define OFF_BL  (3 * TILE_H)
#define STG_H   (4 * TILE_H)              // 20480 halves / stage
#define SMEM_BYTES (2 * STG_H * 2)        // 81920 B

// ---------------------------------------------------------------------------
// Device scratch (device globals: allowed)
// ---------------------------------------------------------------------------
#define ELEMS ((size_t)Bn * 1024 * 1024)
__device__ __half g_Shi[ELEMS], g_Slo[ELEMS];
__device__ __half g_Whi[1024 * 1024], g_Wlo[1024 * 1024];
__device__ __half g_Hhi[ELEMS], g_Hlo[ELEMS];
__device__ __half g_Thi[ELEMS], g_Tlo[ELEMS];     // H transposed
__device__ __half g_SPhi[ELEMS], g_SPlo[ELEMS];   // GEMM1 out
__device__ __half g_Phi[ELEMS], g_Plo[ELEMS];     // softmax out
__device__ float  g_score[ELEMS];

// ---------------------------------------------------------------------------
// Helpers
// ---------------------------------------------------------------------------
__device__ __forceinline__ uint32_t smem_u32(const void* p) {
    return (uint32_t)__cvta_generic_to_shared(p);
}
__device__ __forceinline__ void cp16(uint32_t dst, const void* src) {
    asm volatile("cp.async.cg.shared.global [%0], [%1], 16;\n"
                 :: "r"(dst), "l"(src) : "memory");
}
#define CP_COMMIT() asm volatile("cp.async.commit_group;\n" ::: "memory")
#define CP_WAIT(n)  asm volatile("cp.async.wait_group %0;\n" :: "n"(n) : "memory")

#define LDSM4(r, a)                                                            \
    asm volatile("ldmatrix.sync.aligned.m8n8.x4.shared.b16 {%0,%1,%2,%3}, [%4];" \
        : "=r"((r)[0]), "=r"((r)[1]), "=r"((r)[2]), "=r"((r)[3]) : "r"(a))

#define MMA16816(c, a, b0v, b1v)                                               \
    asm volatile("mma.sync.aligned.m16n8k16.row.col.f32.f16.f16.f32 "          \
        "{%0,%1,%2,%3}, {%4,%5,%6,%7}, {%8,%9}, {%0,%1,%2,%3};"                \
        : "+f"((c)[0]), "+f"((c)[1]), "+f"((c)[2]), "+f"((c)[3])               \
        : "r"((a)[0]), "r"((a)[1]), "r"((a)[2]), "r"((a)[3]),                  \
          "r"(b0v), "r"(b1v))

__device__ __forceinline__ void split1(float x, __half& h, __half& l) {
    h = __float2half_rn(x);
    l = __float2half_rn(x - __half2float(h));
}

// ---------------------------------------------------------------------------
// HMMA NT GEMM (C[m][n] = sum_k A[m][k]*B[n][k]), fp16 hi/lo 3-pass split.
// MODE 0: +bias[n], write __half hi/lo.  MODE 1: +mask, write fp32.
// MODE 2: write fp32.
// ---------------------------------------------------------------------------
template <int MODE>
__global__ __launch_bounds__(256) void gemm3x(
    const __half* __restrict__ Ahi, const __half* __restrict__ Alo,
    const __half* __restrict__ Bhi, const __half* __restrict__ Blo,
    size_t sA, size_t sB,
    const float* __restrict__ bias,
    const float* __restrict__ mask, size_t sMask,
    float* __restrict__ outF, size_t sOutF,
    __half* __restrict__ outHi, __half* __restrict__ outLo, size_t sOutB)
{
    extern __shared__ __half sm[];

    const int tid  = threadIdx.x;
    const int lane = tid & 31;
    const int wid  = tid >> 5;
    const int m0 = blockIdx.y * 128, n0 = blockIdx.x * 128, bz = blockIdx.z;

    Ahi += (size_t)bz * sA;  Alo += (size_t)bz * sA;
    Bhi += (size_t)bz * sB;  Blo += (size_t)bz * sB;

    const uint32_t sbase = smem_u32(sm);

    // --- gmem->smem loader mapping: thread -> (row, 2x16B segs) per tile
    const int lr = tid >> 1;                 // 0..127
    const int sg = (tid & 1) * 2;            // 0 or 2 (16B segs sg, sg+1)
    const uint32_t s_off = (uint32_t)lr * (STRD * 2) + (uint32_t)sg * 16;

    auto load_stage = [&](int stg, int c) {
        const uint32_t sb = sbase + (uint32_t)stg * (STG_H * 2);
        const size_t kof = (size_t)c * BK + (size_t)sg * 8;
        const __half* pah = Ahi + (size_t)(m0 + lr) * KDIM + kof;
        const __half* pal = Alo + (size_t)(m0 + lr) * KDIM + kof;
        const __half* pbh = Bhi + (size_t)(n0 + lr) * KDIM + kof;
        const __half* pbl = Blo + (size_t)(n0 + lr) * KDIM + kof;
        cp16(sb + OFF_AH * 2 + s_off,      pah);
        cp16(sb + OFF_AH * 2 + s_off + 16, pah + 8);
        cp16(sb + OFF_AL * 2 + s_off,      pal);
        cp16(sb + OFF_AL * 2 + s_off + 16, pal + 8);
        cp16(sb + OFF_BH * 2 + s_off,      pbh);
        cp16(sb + OFF_BH * 2 + s_off + 16, pbh + 8);
        cp16(sb + OFF_BL * 2 + s_off,      pbl);
        cp16(sb + OFF_BL * 2 + s_off + 16, pbl + 8);
    };

    // --- per-warp compute mapping
    const int wm = (wid & 1) * 64;           // warp M offset in tile
    const int wn = (wid >> 1) * 32;          // warp N offset in tile
    const uint32_t lrow = (uint32_t)(lane & 15);
    const uint32_t lk8  = (uint32_t)(lane >> 4) * 8;

    float acc[4][4][4];
    #pragma unroll
    for (int i = 0; i < 4; i++)
        #pragma unroll
        for (int j = 0; j < 4; j++)
            #pragma unroll
            for (int r = 0; r < 4; r++) acc[i][j][r] = 0.0f;

    load_stage(0, 0);
    CP_COMMIT();

    for (int c = 0; c < NCHUNK; ++c) {
        if (c + 1 < NCHUNK) {
            load_stage((c + 1) & 1, c + 1);
            CP_COMMIT();
            CP_WAIT(1);
        } else {
            CP_WAIT(0);
        }
        __syncthreads();

        const uint32_t sb = sbase + (uint32_t)(c & 1) * (STG_H * 2);
        #pragma unroll
        for (int ks = 0; ks < 2; ++ks) {
            const uint32_t kb = (uint32_t)ks * 16;
            uint32_t ah[4][4], al[4][4], bh[2][4], bl[2][4];
            #pragma unroll
            for (int smi = 0; smi < 4; ++smi) {
                const uint32_t row = (uint32_t)(wm + smi * 16) + lrow;
                const uint32_t base = sb + 2u * (row * STRD + kb + lk8);
                LDSM4(ah[smi], base + OFF_AH * 2);
                LDSM4(al[smi], base + OFF_AL * 2);
            }
            #pragma unroll
            for (int g = 0; g < 2; ++g) {
                const uint32_t row = (uint32_t)(wn + g * 16) + lrow;
                const uint32_t base = sb + 2u * (row * STRD + kb + lk8);
                LDSM4(bh[g], base + OFF_BH * 2);
                LDSM4(bl[g], base + OFF_BL * 2);
            }
            #pragma unroll
            for (int smi = 0; smi < 4; ++smi) {
                #pragma unroll
                for (int sn = 0; sn < 4; ++sn) {
                    const int g = sn >> 1, s = sn & 1;
                    MMA16816(acc[smi][sn], ah[smi], bh[g][s], bh[g][s + 2]);
                    MMA16816(acc[smi][sn], al[smi], bh[g][s], bh[g][s + 2]);
                    MMA16816(acc[smi][sn], ah[smi], bl[g][s], bl[g][s + 2]);
                }
            }
        }
        __syncthreads();
    }

    // --- epilogue
    #pragma unroll
    for (int smi = 0; smi < 4; ++smi) {
        const int gm0 = m0 + wm + smi * 16 + (lane >> 2);
        #pragma unroll
        for (int hr = 0; hr < 2; ++hr) {
            const int gm = gm0 + hr * 8;
            #pragma unroll
            for (int sn = 0; sn < 4; ++sn) {
                const int gn = n0 + wn + sn * 8 + 2 * (lane & 3);
                float v0 = acc[smi][sn][hr * 2 + 0];
                float v1 = acc[smi][sn][hr * 2 + 1];
                if (MODE == 0) {
                    v0 += bias[gn]; v1 += bias[gn + 1];
                    __half h0, h1, l0, l1;
                    split1(v0, h0, l0); split1(v1, h1, l1);
                    const size_t off = (size_t)bz * sOutB + (size_t)gm * 1024 + gn;
                    *reinterpret_cast<__half2*>(outHi + off) = __halves2half2(h0, h1);
                    *reinterpret_cast<__half2*>(outLo + off) = __halves2half2(l0, l1);
                } else if (MODE == 1) {
                    const size_t moff = (size_t)bz * sMask + (size_t)gm * 1024 + gn;
                    const float2 mk = *reinterpret_cast<const float2*>(&mask[moff]);
                    v0 += mk.x; v1 += mk.y;
                    const size_t off = (size_t)bz * sOutF + (size_t)gm * 1024 + gn;
                    float2 o; o.x = v0; o.y = v1;
                    *reinterpret_cast<float2*>(&outF[off]) = o;
                } else {
                    const size_t off = (size_t)bz * sOutF + (size_t)gm * 1024 + gn;
                    float2 o; o.x = v0; o.y = v1;
                    *reinterpret_cast<float2*>(&outF[off]) = o;
                }
            }
        }
    }
}

// ---------------------------------------------------------------------------
// fp32 -> fp16 hi/lo split (elementwise)
// ---------------------------------------------------------------------------
__global__ __launch_bounds__(256) void split_plain(
    const float* __restrict__ x, __half* __restrict__ hi,
    __half* __restrict__ lo, size_t n)
{
    const size_t i = ((size_t)blockIdx.x * 256 + threadIdx.x) * 4;
    if (i >= n) return;
    const float4 v = *reinterpret_cast<const float4*>(&x[i]);
    __half h0, h1, h2, h3, l0, l1, l2, l3;
    split1(v.x, h0, l0); split1(v.y, h1, l1);
    split1(v.z, h2, l2); split1(v.w, h3, l3);
    __half2 hv[2] = { __halves2half2(h0, h1), __halves2half2(h2, h3) };
    __half2 lv[2] = { __halves2half2(l0, l1), __halves2half2(l2, l3) };
    *reinterpret_cast<uint2*>(hi + i) = *reinterpret_cast<uint2*>(hv);
    *reinterpret_cast<uint2*>(lo + i) = *reinterpret_cast<uint2*>(lv);
}

// ---------------------------------------------------------------------------
// H: split to hi/lo AND transposed hi/lo ([B][D2][LH])
// ---------------------------------------------------------------------------
__global__ __launch_bounds__(256) void split_h(
    const float* __restrict__ H,
    __half* __restrict__ Hhi, __half* __restrict__ Hlo,
    __half* __restrict__ Thi, __half* __restrict__ Tlo)
{
    __shared__ float tile[32][33];
    const int b = blockIdx.z;
    const int t0 = blockIdx.y * 32;   // LH dim
    const int e0 = blockIdx.x * 32;   // D2 dim
    const int tx = threadIdx.x & 31, ty = threadIdx.x >> 5;
    const size_t base = (size_t)b * 1024 * 1024;

    #pragma unroll
    for (int i = 0; i < 4; ++i) {
        const int r = ty + i * 8;
        const float v = H[base + (size_t)(t0 + r) * 1024 + e0 + tx];
        tile[r][tx] = v;
        __half h, l; split1(v, h, l);
        const size_t off = base + (size_t)(t0 + r) * 1024 + e0 + tx;
        Hhi[off] = h; Hlo[off] = l;
    }
    __syncthreads();
    #pragma unroll
    for (int i = 0; i < 4; ++i) {
        const int r = ty + i * 8;
        const float v = tile[tx][r];
        __half h, l; split1(v, h, l);
        const size_t off = base + (size_t)(e0 + r) * 1024 + t0 + tx;
        Thi[off] = h; Tlo[off] = l;
    }
}

// ---------------------------------------------------------------------------
// Row softmax (len 1024) fp32 in, fp16 hi/lo out
// ---------------------------------------------------------------------------
__global__ __launch_bounds__(256) void softmax_split(
    const float* __restrict__ sc,
    __half* __restrict__ phi, __half* __restrict__ plo)
{
    __shared__ float red[8];
    const size_t row = blockIdx.x;
    const float* p = sc + row * 1024;
    const int tid = threadIdx.x, lane = tid & 31, wid = tid >> 5;

    float v[4];
    float mx = -INFINITY;
    #pragma unroll
    for (int i = 0; i < 4; i++) { v[i] = p[tid + i * 256]; mx = fmaxf(mx, v[i]); }
    #pragma unroll
    for (int off = 16; off > 0; off >>= 1)
        mx = fmaxf(mx, __shfl_xor_sync(0xffffffffu, mx, off));
    if (lane == 0) red[wid] = mx;
    __syncthreads();
    {
        float m = red[lane & 7];
        #pragma unroll
        for (int off = 4; off > 0; off >>= 1)
            m = fmaxf(m, __shfl_xor_sync(0xffffffffu, m, off));
        mx = m;
    }
    float s = 0.0f;
    #pragma unroll
    for (int i = 0; i < 4; i++) { v[i] = expf(v[i] - mx); s += v[i]; }
    #pragma unroll
    for (int off = 16; off > 0; off >>= 1)
        s += __shfl_xor_sync(0xffffffffu, s, off);
    __syncthreads();
    if (lane == 0) red[wid] = s;
    __syncthreads();
    {
        float t = red[lane & 7];
        #pragma unroll
        for (int off = 4; off > 0; off >>= 1)
            t += __shfl_xor_sync(0xffffffffu, t, off);
        s = t;
    }
    const float inv = 1.0f / s;
    #pragma unroll
    for (int i = 0; i < 4; i++) {
        const float pv = v[i] * inv;
        __half h, l; split1(pv, h, l);
        phi[row * 1024 + tid + i * 256] = h;
        plo[row * 1024 + tid + i * 256] = l;
    }
}

// ---------------------------------------------------------------------------
// Launch
// ---------------------------------------------------------------------------
extern "C" void kernel_launch(void* const* d_in, const int* in_sizes, int n_in,
                              void* d_out, int out_size)
{
    const float* S    = (const float*)d_in[0];
    const float* H    = (const float*)d_in[1];
    const float* mask = (const float*)d_in[2];
    const float* Ww   = (const float*)d_in[3];
    const float* Wb   = (const float*)d_in[4];
    float* out = (float*)d_out;

    __half *Shi, *Slo, *Whi, *Wlo, *Hhi, *Hlo, *Thi, *Tlo;
    __half *SPhi, *SPlo, *Phi, *Plo;
    float* score;
    cudaGetSymbolAddress((void**)&Shi, g_Shi);   cudaGetSymbolAddress((void**)&Slo, g_Slo);
    cudaGetSymbolAddress((void**)&Whi, g_Whi);   cudaGetSymbolAddress((void**)&Wlo, g_Wlo);
    cudaGetSymbolAddress((void**)&Hhi, g_Hhi);   cudaGetSymbolAddress((void**)&Hlo, g_Hlo);
    cudaGetSymbolAddress((void**)&Thi, g_Thi);   cudaGetSymbolAddress((void**)&Tlo, g_Tlo);
    cudaGetSymbolAddress((void**)&SPhi, g_SPhi); cudaGetSymbolAddress((void**)&SPlo, g_SPlo);
    cudaGetSymbolAddress((void**)&Phi, g_Phi);   cudaGetSymbolAddress((void**)&Plo, g_Plo);
    cudaGetSymbolAddress((void**)&score, g_score);

    cudaFuncSetAttribute(gemm3x<0>, cudaFuncAttributeMaxDynamicSharedMemorySize, SMEM_BYTES);
    cudaFuncSetAttribute(gemm3x<1>, cudaFuncAttributeMaxDynamicSharedMemorySize, SMEM_BYTES);
    cudaFuncSetAttribute(gemm3x<2>, cudaFuncAttributeMaxDynamicSharedMemorySize, SMEM_BYTES);

    // splits
    split_plain<<<(unsigned)(ELEMS / 1024), 256>>>(S, Shi, Slo, ELEMS);
    split_plain<<<1024, 256>>>(Ww, Whi, Wlo, (size_t)1024 * 1024);
    split_h<<<dim3(32, 32, Bn), 256>>>(H, Hhi, Hlo, Thi, Tlo);

    dim3 grid(8, 8, Bn);
    // 1) S_ = S @ W^T + b  (W shared across batch: sB = 0)
    gemm3x<0><<<grid, 256, SMEM_BYTES>>>(Shi, Slo, Whi, Wlo, PB, 0,
                                         Wb, nullptr, 0, nullptr, 0, SPhi, SPlo, PB);
    // 2) score = S_ @ H^T + mask
    gemm3x<1><<<grid, 256, SMEM_BYTES>>>(SPhi, SPlo, Hhi, Hlo, PB, PB,
                                         nullptr, mask, PB, score, PB, nullptr, nullptr, 0);
    // 3) softmax + split
    softmax_split<<<Bn * 1024, 256>>>(score, Phi, Plo);
    // 4) out = P @ H  (B = H^T, pre-transposed)
    gemm3x<2><<<grid, 256, SMEM_BYTES>>>(Phi, Plo, Thi, Tlo, PB, PB,
                                         nullptr, nullptr, 0, out, PB, nullptr, nullptr, 0);
}

// round 4
// speedup vs baseline: 2.0814x; 1.7038x over previous
#include <cuda_runtime.h>
#include <cuda_fp16.h>
#include <math.h>
#include <stdint.h>

// Problem constants
#define Bn    16
#define KDIM  1024
#define PB    ((size_t)1024 * 1024)

// GEMM tiling
#define BK      32            // halves per K chunk (64B per row)
#define NCHUNK  (KDIM / BK)   // 32
#define TILE_B  8192          // bytes per 128x32-half tile (swizzled, no pad)
#define OFF_AH  0
#define OFF_AL  (1 * TILE_B)
#define OFF_BH  (2 * TILE_B)
#define OFF_BL  (3 * TILE_B)
#define STG_B   (4 * TILE_B)          // 32 KB / stage
#define NSTG    3
#define SMEM_BYTES (NSTG * STG_B)     // 96 KB

// ---------------------------------------------------------------------------
// Device scratch (device globals: allowed)
// ---------------------------------------------------------------------------
#define ELEMS ((size_t)Bn * 1024 * 1024)
__device__ __half g_Shi[ELEMS], g_Slo[ELEMS];
__device__ __half g_Whi[1024 * 1024], g_Wlo[1024 * 1024];
__device__ __half g_Hhi[ELEMS], g_Hlo[ELEMS];
__device__ __half g_Thi[ELEMS], g_Tlo[ELEMS];     // H transposed
__device__ __half g_SPhi[ELEMS], g_SPlo[ELEMS];   // GEMM1 out
__device__ __half g_Phi[ELEMS], g_Plo[ELEMS];     // softmax out
__device__ float  g_score[ELEMS];

// ---------------------------------------------------------------------------
// Helpers
// ---------------------------------------------------------------------------
__device__ __forceinline__ uint32_t smem_u32(const void* p) {
    return (uint32_t)__cvta_generic_to_shared(p);
}
__device__ __forceinline__ void cp16(uint32_t dst, const void* src) {
    asm volatile("cp.async.cg.shared.global [%0], [%1], 16;\n"
                 :: "r"(dst), "l"(src) : "memory");
}
#define CP_COMMIT() asm volatile("cp.async.commit_group;\n" ::: "memory")
#define CP_WAIT(n)  asm volatile("cp.async.wait_group %0;\n" :: "n"(n) : "memory")

// Swizzled byte offset within a 128x32-half tile (rows of 64B packed).
// r = row 0..127, c = 16B segment 0..3. All 8 consecutive rows at fixed c map
// to 8 distinct 16B phases of a 128B line -> ldmatrix conflict-free.
__device__ __forceinline__ uint32_t swz(uint32_t r, uint32_t c) {
    return (r >> 1) * 128u + (((((r & 1u) << 2) | (c ^ ((r >> 1) & 3u)))) << 4);
}

#define LDSM4(r, a)                                                            \
    asm volatile("ldmatrix.sync.aligned.m8n8.x4.shared.b16 {%0,%1,%2,%3}, [%4];" \
        : "=r"((r)[0]), "=r"((r)[1]), "=r"((r)[2]), "=r"((r)[3]) : "r"(a))

#define MMA16816(c, a, b0v, b1v)                                               \
    asm volatile("mma.sync.aligned.m16n8k16.row.col.f32.f16.f16.f32 "          \
        "{%0,%1,%2,%3}, {%4,%5,%6,%7}, {%8,%9}, {%0,%1,%2,%3};"                \
        : "+f"((c)[0]), "+f"((c)[1]), "+f"((c)[2]), "+f"((c)[3])               \
        : "r"((a)[0]), "r"((a)[1]), "r"((a)[2]), "r"((a)[3]),                  \
          "r"(b0v), "r"(b1v))

__device__ __forceinline__ void split1(float x, __half& h, __half& l) {
    h = __float2half_rn(x);
    l = __float2half_rn(x - __half2float(h));
}

// ---------------------------------------------------------------------------
// HMMA NT GEMM (C[m][n] = sum_k A[m][k]*B[n][k]), fp16 hi/lo 3-pass split.
// 3-stage cp.async pipeline, 1 barrier per K chunk, 2 CTAs/SM.
// MODE 0: +bias[n], write __half hi/lo.  MODE 1: +mask, write fp32.
// MODE 2: write fp32.
// ---------------------------------------------------------------------------
template <int MODE>
__global__ __launch_bounds__(256, 2) void gemm3x(
    const __half* __restrict__ Ahi, const __half* __restrict__ Alo,
    const __half* __restrict__ Bhi, const __half* __restrict__ Blo,
    size_t sA, size_t sB,
    const float* __restrict__ bias,
    const float* __restrict__ mask, size_t sMask,
    float* __restrict__ outF, size_t sOutF,
    __half* __restrict__ outHi, __half* __restrict__ outLo, size_t sOutB)
{
    extern __shared__ __half sm[];

    const int tid  = threadIdx.x;
    const int lane = tid & 31;
    const int wid  = tid >> 5;
    const int m0 = blockIdx.y * 128, n0 = blockIdx.x * 128, bz = blockIdx.z;

    Ahi += (size_t)bz * sA;  Alo += (size_t)bz * sA;
    Bhi += (size_t)bz * sB;  Blo += (size_t)bz * sB;

    const uint32_t sbase = smem_u32(sm);

    // --- gmem->smem loader mapping: thread -> (row, 2x16B segs) per tile
    const int lr = tid >> 1;                 // 0..127
    const int c0 = (tid & 1) * 2;            // seg 0 or 2
    const uint32_t sw0 = swz((uint32_t)lr, (uint32_t)c0);
    const uint32_t sw1 = swz((uint32_t)lr, (uint32_t)c0 + 1);

    auto load_stage = [&](int c) {
        const uint32_t sb = sbase + (uint32_t)(c % NSTG) * STG_B;
        const size_t kof = (size_t)c * BK + (size_t)c0 * 8;
        const __half* pah = Ahi + (size_t)(m0 + lr) * KDIM + kof;
        const __half* pal = Alo + (size_t)(m0 + lr) * KDIM + kof;
        const __half* pbh = Bhi + (size_t)(n0 + lr) * KDIM + kof;
        const __half* pbl = Blo + (size_t)(n0 + lr) * KDIM + kof;
        cp16(sb + OFF_AH + sw0, pah);
        cp16(sb + OFF_AH + sw1, pah + 8);
        cp16(sb + OFF_AL + sw0, pal);
        cp16(sb + OFF_AL + sw1, pal + 8);
        cp16(sb + OFF_BH + sw0, pbh);
        cp16(sb + OFF_BH + sw1, pbh + 8);
        cp16(sb + OFF_BL + sw0, pbl);
        cp16(sb + OFF_BL + sw1, pbl + 8);
    };

    // --- per-warp compute mapping
    const int wm = (wid & 1) * 64;           // warp M offset in tile
    const int wn = (wid >> 1) * 32;          // warp N offset in tile
    const uint32_t lrow = (uint32_t)(lane & 15);
    const uint32_t chi  = (uint32_t)(lane >> 4);   // 16B seg select (k 0-7 vs 8-15)

    float acc[4][4][4];
    #pragma unroll
    for (int i = 0; i < 4; i++)
        #pragma unroll
        for (int j = 0; j < 4; j++)
            #pragma unroll
            for (int r = 0; r < 4; r++) acc[i][j][r] = 0.0f;

    // Prologue: stages 0, 1
    load_stage(0); CP_COMMIT();
    load_stage(1); CP_COMMIT();

    for (int c = 0; c < NCHUNK; ++c) {
        if (c == NCHUNK - 1) { CP_WAIT(0); } else { CP_WAIT(1); }
        __syncthreads();  // stage c visible; also retires compute(c-1) -> its buffer reusable
        if (c + 2 < NCHUNK) {
            load_stage(c + 2);   // writes buffer (c+2)%3 == (c-1)%3, safe after barrier
            CP_COMMIT();
        }

        const uint32_t sb = sbase + (uint32_t)(c % NSTG) * STG_B;
        #pragma unroll
        for (int ks = 0; ks < 2; ++ks) {
            const uint32_t cseg = (uint32_t)ks * 2 + chi;
            uint32_t ah[4][4], al[4][4], bh[2][4], bl[2][4];
            #pragma unroll
            for (int smi = 0; smi < 4; ++smi) {
                const uint32_t row = (uint32_t)(wm + smi * 16) + lrow;
                const uint32_t so = swz(row, cseg);
                LDSM4(ah[smi], sb + OFF_AH + so);
                LDSM4(al[smi], sb + OFF_AL + so);
            }
            #pragma unroll
            for (int g = 0; g < 2; ++g) {
                const uint32_t row = (uint32_t)(wn + g * 16) + lrow;
                const uint32_t so = swz(row, cseg);
                LDSM4(bh[g], sb + OFF_BH + so);
                LDSM4(bl[g], sb + OFF_BL + so);
            }
            #pragma unroll
            for (int smi = 0; smi < 4; ++smi) {
                #pragma unroll
                for (int sn = 0; sn < 4; ++sn) {
                    const int g = sn >> 1, s = sn & 1;
                    MMA16816(acc[smi][sn], ah[smi], bh[g][s], bh[g][s + 2]);
                    MMA16816(acc[smi][sn], al[smi], bh[g][s], bh[g][s + 2]);
                    MMA16816(acc[smi][sn], ah[smi], bl[g][s], bl[g][s + 2]);
                }
            }
        }
    }

    // --- epilogue
    #pragma unroll
    for (int smi = 0; smi < 4; ++smi) {
        const int gm0 = m0 + wm + smi * 16 + (lane >> 2);
        #pragma unroll
        for (int hr = 0; hr < 2; ++hr) {
            const int gm = gm0 + hr * 8;
            #pragma unroll
            for (int sn = 0; sn < 4; ++sn) {
                const int gn = n0 + wn + sn * 8 + 2 * (lane & 3);
                float v0 = acc[smi][sn][hr * 2 + 0];
                float v1 = acc[smi][sn][hr * 2 + 1];
                if (MODE == 0) {
                    v0 += bias[gn]; v1 += bias[gn + 1];
                    __half h0, h1, l0, l1;
                    split1(v0, h0, l0); split1(v1, h1, l1);
                    const size_t off = (size_t)bz * sOutB + (size_t)gm * 1024 + gn;
                    *reinterpret_cast<__half2*>(outHi + off) = __halves2half2(h0, h1);
                    *reinterpret_cast<__half2*>(outLo + off) = __halves2half2(l0, l1);
                } else if (MODE == 1) {
                    const size_t moff = (size_t)bz * sMask + (size_t)gm * 1024 + gn;
                    const float2 mk = *reinterpret_cast<const float2*>(&mask[moff]);
                    v0 += mk.x; v1 += mk.y;
                    const size_t off = (size_t)bz * sOutF + (size_t)gm * 1024 + gn;
                    float2 o; o.x = v0; o.y = v1;
                    *reinterpret_cast<float2*>(&outF[off]) = o;
                } else {
                    const size_t off = (size_t)bz * sOutF + (size_t)gm * 1024 + gn;
                    float2 o; o.x = v0; o.y = v1;
                    *reinterpret_cast<float2*>(&outF[off]) = o;
                }
            }
        }
    }
}

// ---------------------------------------------------------------------------
// fp32 -> fp16 hi/lo split (elementwise)
// ---------------------------------------------------------------------------
__global__ __launch_bounds__(256) void split_plain(
    const float* __restrict__ x, __half* __restrict__ hi,
    __half* __restrict__ lo, size_t n)
{
    const size_t i = ((size_t)blockIdx.x * 256 + threadIdx.x) * 4;
    if (i >= n) return;
    const float4 v = *reinterpret_cast<const float4*>(&x[i]);
    __half h0, h1, h2, h3, l0, l1, l2, l3;
    split1(v.x, h0, l0); split1(v.y, h1, l1);
    split1(v.z, h2, l2); split1(v.w, h3, l3);
    __half2 hv[2] = { __halves2half2(h0, h1), __halves2half2(h2, h3) };
    __half2 lv[2] = { __halves2half2(l0, l1), __halves2half2(l2, l3) };
    *reinterpret_cast<uint2*>(hi + i) = *reinterpret_cast<uint2*>(hv);
    *reinterpret_cast<uint2*>(lo + i) = *reinterpret_cast<uint2*>(lv);
}

// ---------------------------------------------------------------------------
// H: split to hi/lo AND transposed hi/lo ([B][D2][LH])
// ---------------------------------------------------------------------------
__global__ __launch_bounds__(256) void split_h(
    const float* __restrict__ H,
    __half* __restrict__ Hhi, __half* __restrict__ Hlo,
    __half* __restrict__ Thi, __half* __restrict__ Tlo)
{
    __shared__ float tile[32][33];
    const int b = blockIdx.z;
    const int t0 = blockIdx.y * 32;   // LH dim
    const int e0 = blockIdx.x * 32;   // D2 dim
    const int tx = threadIdx.x & 31, ty = threadIdx.x >> 5;
    const size_t base = (size_t)b * 1024 * 1024;

    #pragma unroll
    for (int i = 0; i < 4; ++i) {
        const int r = ty + i * 8;
        const float v = H[base + (size_t)(t0 + r) * 1024 + e0 + tx];
        tile[r][tx] = v;
        __half h, l; split1(v, h, l);
        const size_t off = base + (size_t)(t0 + r) * 1024 + e0 + tx;
        Hhi[off] = h; Hlo[off] = l;
    }
    __syncthreads();
    #pragma unroll
    for (int i = 0; i < 4; ++i) {
        const int r = ty + i * 8;
        const float v = tile[tx][r];
        __half h, l; split1(v, h, l);
        const size_t off = base + (size_t)(e0 + r) * 1024 + t0 + tx;
        Thi[off] = h; Tlo[off] = l;
    }
}

// ---------------------------------------------------------------------------
// Row softmax (len 1024) fp32 in, fp16 hi/lo out
// ---------------------------------------------------------------------------
__global__ __launch_bounds__(256) void softmax_split(
    const float* __restrict__ sc,
    __half* __restrict__ phi, __half* __restrict__ plo)
{
    __shared__ float red[8];
    const size_t row = blockIdx.x;
    const float* p = sc + row * 1024;
    const int tid = threadIdx.x, lane = tid & 31, wid = tid >> 5;

    float v[4];
    float mx = -INFINITY;
    #pragma unroll
    for (int i = 0; i < 4; i++) { v[i] = p[tid + i * 256]; mx = fmaxf(mx, v[i]); }
    #pragma unroll
    for (int off = 16; off > 0; off >>= 1)
        mx = fmaxf(mx, __shfl_xor_sync(0xffffffffu, mx, off));
    if (lane == 0) red[wid] = mx;
    __syncthreads();
    {
        float m = red[lane & 7];
        #pragma unroll
        for (int off = 4; off > 0; off >>= 1)
            m = fmaxf(m, __shfl_xor_sync(0xffffffffu, m, off));
        mx = m;
    }
    float s = 0.0f;
    #pragma unroll
    for (int i = 0; i < 4; i++) { v[i] = expf(v[i] - mx); s += v[i]; }
    #pragma unroll
    for (int off = 16; off > 0; off >>= 1)
        s += __shfl_xor_sync(0xffffffffu, s, off);
    __syncthreads();
    if (lane == 0) red[wid] = s;
    __syncthreads();
    {
        float t = red[lane & 7];
        #pragma unroll
        for (int off = 4; off > 0; off >>= 1)
            t += __shfl_xor_sync(0xffffffffu, t, off);
        s = t;
    }
    const float inv = 1.0f / s;
    #pragma unroll
    for (int i = 0; i < 4; i++) {
        const float pv = v[i] * inv;
        __half h, l; split1(pv, h, l);
        phi[row * 1024 + tid + i * 256] = h;
        plo[row * 1024 + tid + i * 256] = l;
    }
}

// ---------------------------------------------------------------------------
// Launch
// ---------------------------------------------------------------------------
extern "C" void kernel_launch(void* const* d_in, const int* in_sizes, int n_in,
                              void* d_out, int out_size)
{
    const float* S    = (const float*)d_in[0];
    const float* H    = (const float*)d_in[1];
    const float* mask = (const float*)d_in[2];
    const float* Ww   = (const float*)d_in[3];
    const float* Wb   = (const float*)d_in[4];
    float* out = (float*)d_out;

    __half *Shi, *Slo, *Whi, *Wlo, *Hhi, *Hlo, *Thi, *Tlo;
    __half *SPhi, *SPlo, *Phi, *Plo;
    float* score;
    cudaGetSymbolAddress((void**)&Shi, g_Shi);   cudaGetSymbolAddress((void**)&Slo, g_Slo);
    cudaGetSymbolAddress((void**)&Whi, g_Whi);   cudaGetSymbolAddress((void**)&Wlo, g_Wlo);
    cudaGetSymbolAddress((void**)&Hhi, g_Hhi);   cudaGetSymbolAddress((void**)&Hlo, g_Hlo);
    cudaGetSymbolAddress((void**)&Thi, g_Thi);   cudaGetSymbolAddress((void**)&Tlo, g_Tlo);
    cudaGetSymbolAddress((void**)&SPhi, g_SPhi); cudaGetSymbolAddress((void**)&SPlo, g_SPlo);
    cudaGetSymbolAddress((void**)&Phi, g_Phi);   cudaGetSymbolAddress((void**)&Plo, g_Plo);
    cudaGetSymbolAddress((void**)&score, g_score);

    cudaFuncSetAttribute(gemm3x<0>, cudaFuncAttributeMaxDynamicSharedMemorySize, SMEM_BYTES);
    cudaFuncSetAttribute(gemm3x<1>, cudaFuncAttributeMaxDynamicSharedMemorySize, SMEM_BYTES);
    cudaFuncSetAttribute(gemm3x<2>, cudaFuncAttributeMaxDynamicSharedMemorySize, SMEM_BYTES);

    // splits
    split_plain<<<(unsigned)(ELEMS / 1024), 256>>>(S, Shi, Slo, ELEMS);
    split_plain<<<1024, 256>>>(Ww, Whi, Wlo, (size_t)1024 * 1024);
    split_h<<<dim3(32, 32, Bn), 256>>>(H, Hhi, Hlo, Thi, Tlo);

    dim3 grid(8, 8, Bn);
    // 1) S_ = S @ W^T + b  (W shared across batch: sB = 0)
    gemm3x<0><<<grid, 256, SMEM_BYTES>>>(Shi, Slo, Whi, Wlo, PB, 0,
                                         Wb, nullptr, 0, nullptr, 0, SPhi, SPlo, PB);
    // 2) score = S_ @ H^T + mask
    gemm3x<1><<<grid, 256, SMEM_BYTES>>>(SPhi, SPlo, Hhi, Hlo, PB, PB,
                                         nullptr, mask, PB, score, PB, nullptr, nullptr, 0);
    // 3) softmax + split
    softmax_split<<<Bn * 1024, 256>>>(score, Phi, Plo);
    // 4) out = P @ H  (B = H^T, pre-transposed)
    gemm3x<2><<<grid, 256, SMEM_BYTES>>>(Phi, Plo, Thi, Tlo, PB, PB,
                                         nullptr, nullptr, 0, out, PB, nullptr, nullptr, 0);
}